// round 15
// baseline (speedup 1.0000x reference)
#include <cuda_runtime.h>
#include <math.h>

#define N_ 32
#define O_ 2048
#define I_ 4096
#define I4_ (I_/4)          // 1024
#define E_ 3
#define D_ 8
#define H_ 16
#define SELF_W 0.7f
#define OB 4                // o-rows per thread

// Scratch (no allocs allowed)
__device__ float4 g_wnm4[N_ * I4_];   // w[n]*mask[n][i]/norm[i]
__device__ float4 g_a4[I4_];          // 0.7*tm[i]/norm[i]

// ---------------------------------------------------------------------------
// Fused prologue: every block's warp 0 redundantly computes the 32 attention
// weights (concurrent across blocks), then all threads compute the
// per-column coefficients + bias output.  32 blocks x 128 threads.
// ---------------------------------------------------------------------------
__global__ void __launch_bounds__(128)
prologue_kernel(const float* __restrict__ edge_feats,
                const float* __restrict__ node_feats,
                const float* __restrict__ W1e, const float* __restrict__ b1e,
                const float* __restrict__ W2e, const float* __restrict__ b2e,
                const float* __restrict__ W1n, const float* __restrict__ b1n,
                const float* __restrict__ W2n, const float* __restrict__ b2n,
                const float* __restrict__ target_b,
                const float* __restrict__ neighbor_b,
                const int*   __restrict__ target_mask,
                const int*   __restrict__ neighbor_masks,
                float* __restrict__ out_b)
{
    __shared__ float w_s[N_];
    const int tid = threadIdx.x;

    if (tid < N_) {
        const int n = tid;
        float logit_e = b2e[0];
        #pragma unroll
        for (int h = 0; h < H_; h++) {
            float acc = b1e[h];
            #pragma unroll
            for (int e = 0; e < E_; e++)
                acc += edge_feats[n * E_ + e] * W1e[e * H_ + h];
            logit_e += tanhf(acc) * W2e[h];
        }
        const float score = 1.f / (1.f + expf(-logit_e));

        float logit_n = b2n[0];
        #pragma unroll
        for (int h = 0; h < H_; h++) {
            float acc = b1n[h];
            #pragma unroll
            for (int d = 0; d < D_; d++)
                acc += node_feats[n * D_ + d] * W1n[d * H_ + h];
            logit_n += tanhf(acc) * W2n[h];
        }
        const float cond = 1.f / (1.f + expf(-logit_n));

        const float s = score * cond;
        float m = s;
        #pragma unroll
        for (int off = 16; off; off >>= 1)
            m = fmaxf(m, __shfl_xor_sync(0xffffffffu, m, off));
        const float ex = expf(s - m);
        float sum = ex;
        #pragma unroll
        for (int off = 16; off; off >>= 1)
            sum += __shfl_xor_sync(0xffffffffu, sum, off);
        w_s[n] = (1.f - SELF_W) * ex / sum;
    }
    __syncthreads();

    float* g_wnm = (float*)g_wnm4;
    float* g_a   = (float*)g_a4;

    const int i = blockIdx.x * 128 + tid;          // [0, 4096)
    {
        const float tm = (float)target_mask[i];
        float wn[N_];
        float norm = 1e-8f + SELF_W * tm;
        #pragma unroll
        for (int n = 0; n < N_; n++) {
            wn[n] = w_s[n] * (float)neighbor_masks[n * I_ + i];
            norm += wn[n];
        }
        const float inv = 1.f / norm;
        g_a[i] = SELF_W * tm * inv;
        #pragma unroll
        for (int n = 0; n < N_; n++)
            g_wnm[n * I_ + i] = wn[n] * inv;
    }

    if (i < O_) {
        float acc = SELF_W * target_b[i];
        #pragma unroll
        for (int n = 0; n < N_; n++)
            acc += w_s[n] * neighbor_b[n * O_ + i];
        out_b[i] = acc;
    }
}

// ---------------------------------------------------------------------------
// Main: out_W[o,i] = target_W[o,i]*a[i] + sum_n wnm[n,i]*neighbor_W[n,o,i]
// R2/R4/R7 winner structure: persistent grid-stride, idx recomputed per
// iteration (short live ranges -> 64 regs -> 4 blocks/SM), OB=4 for maximum
// wnm register reuse. PDL: blocks are scheduled while the prologue runs;
// gridDepSync gates the first read of g_a4 / g_wnm4.
// ---------------------------------------------------------------------------
#define MAIN_BLOCKS 592     // 148 SMs * 4 resident blocks
#define MAIN_THREADS 256

__global__ void __launch_bounds__(MAIN_THREADS)
main_kernel(const float4* __restrict__ tW,
            const float4* __restrict__ nW,
            float4* __restrict__ outW)
{
    cudaGridDependencySynchronize();

    const int total = (O_ / OB) * I4_;   // 524288 tiles
    for (int idx = blockIdx.x * MAIN_THREADS + threadIdx.x;
         idx < total;
         idx += MAIN_BLOCKS * MAIN_THREADS) {

        const int i4 = idx & (I4_ - 1);
        const int o0 = (idx >> 10) * OB;

        const float4 a = g_a4[i4];
        float4 acc[OB];
        #pragma unroll
        for (int oo = 0; oo < OB; oo++) {
            const float4 t = __ldcs(&tW[(size_t)(o0 + oo) * I4_ + i4]);
            acc[oo].x = t.x * a.x;
            acc[oo].y = t.y * a.y;
            acc[oo].z = t.z * a.z;
            acc[oo].w = t.w * a.w;
        }

        #pragma unroll 4
        for (int n = 0; n < N_; n++) {
            const float4 wv = g_wnm4[n * I4_ + i4];          // L1/L2-resident
            const size_t base = (size_t)n * (O_ * I4_);
            #pragma unroll
            for (int oo = 0; oo < OB; oo++) {
                const float4 Wv = __ldcs(&nW[base + (size_t)(o0 + oo) * I4_ + i4]);
                acc[oo].x += wv.x * Wv.x;
                acc[oo].y += wv.y * Wv.y;
                acc[oo].z += wv.z * Wv.z;
                acc[oo].w += wv.w * Wv.w;
            }
        }

        #pragma unroll
        for (int oo = 0; oo < OB; oo++)
            __stcs(&outW[(size_t)(o0 + oo) * I4_ + i4], acc[oo]);
    }
}

// ---------------------------------------------------------------------------
extern "C" void kernel_launch(void* const* d_in, const int* in_sizes, int n_in,
                              void* d_out, int out_size)
{
    const float* edge_feats     = (const float*)d_in[0];
    const float* node_feats     = (const float*)d_in[1];
    const float* W1e            = (const float*)d_in[2];
    const float* b1e            = (const float*)d_in[3];
    const float* W2e            = (const float*)d_in[4];
    const float* b2e            = (const float*)d_in[5];
    const float* W1n            = (const float*)d_in[6];
    const float* b1n            = (const float*)d_in[7];
    const float* W2n            = (const float*)d_in[8];
    const float* b2n            = (const float*)d_in[9];
    const float* target_W       = (const float*)d_in[10];
    const float* neighbor_W     = (const float*)d_in[11];
    const float* target_b       = (const float*)d_in[12];
    const float* neighbor_b     = (const float*)d_in[13];
    const int*   target_mask    = (const int*)d_in[14];
    const int*   neighbor_masks = (const int*)d_in[15];

    float* out   = (float*)d_out;
    float* out_b = out + (size_t)O_ * I_;

    prologue_kernel<<<I_ / 128, 128>>>(edge_feats, node_feats,
                                       W1e, b1e, W2e, b2e,
                                       W1n, b1n, W2n, b2n,
                                       target_b, neighbor_b,
                                       target_mask, neighbor_masks,
                                       out_b);

    // PDL: main blocks scheduled while the prologue runs; gridDepSync inside
    // gates reads of g_a4/g_wnm4.
    {
        cudaLaunchConfig_t cfg = {};
        cfg.gridDim  = dim3(MAIN_BLOCKS, 1, 1);
        cfg.blockDim = dim3(MAIN_THREADS, 1, 1);
        cfg.dynamicSmemBytes = 0;
        cfg.stream = 0;

        cudaLaunchAttribute attrs[1];
        attrs[0].id = cudaLaunchAttributeProgrammaticStreamSerialization;
        attrs[0].val.programmaticStreamSerializationAllowed = 1;
        cfg.attrs = attrs;
        cfg.numAttrs = 1;

        cudaLaunchKernelEx(&cfg, main_kernel,
                           (const float4*)target_W,
                           (const float4*)neighbor_W,
                           (float4*)out);
    }
}

// round 16
// speedup vs baseline: 1.0015x; 1.0015x over previous
#include <cuda_runtime.h>
#include <math.h>

#define N_ 32
#define O_ 2048
#define I_ 4096
#define I4_ (I_/4)          // 1024
#define E_ 3
#define D_ 8
#define H_ 16
#define SELF_W 0.7f
#define OB 4                // o-rows per thread

// Scratch (no allocs allowed)
__device__ float4 g_wnm4[N_ * I4_];   // w[n]*mask[n][i]/norm[i]
__device__ float4 g_a4[I4_];          // 0.7*tm[i]/norm[i]

// ---------------------------------------------------------------------------
// Fused prologue: every block's warp 0 redundantly computes the 32 attention
// weights (concurrent across blocks), then all threads compute the
// per-column coefficients + bias output.  64 blocks x 64 threads (small
// blocks -> shorter last-block finish time -> smaller PDL shadow).
// Fast-math intrinsics shorten the serial MLP chain; rel error ~1e-6 vs the
// 1e-3 threshold.
// ---------------------------------------------------------------------------
#define PRO_BLOCKS 64
#define PRO_THREADS 64

__global__ void __launch_bounds__(PRO_THREADS)
prologue_kernel(const float* __restrict__ edge_feats,
                const float* __restrict__ node_feats,
                const float* __restrict__ W1e, const float* __restrict__ b1e,
                const float* __restrict__ W2e, const float* __restrict__ b2e,
                const float* __restrict__ W1n, const float* __restrict__ b1n,
                const float* __restrict__ W2n, const float* __restrict__ b2n,
                const float* __restrict__ target_b,
                const float* __restrict__ neighbor_b,
                const int*   __restrict__ target_mask,
                const int*   __restrict__ neighbor_masks,
                float* __restrict__ out_b)
{
    __shared__ float w_s[N_];
    const int tid = threadIdx.x;

    if (tid < N_) {
        const int n = tid;
        float logit_e = b2e[0];
        #pragma unroll
        for (int h = 0; h < H_; h++) {
            float acc = b1e[h];
            #pragma unroll
            for (int e = 0; e < E_; e++)
                acc += edge_feats[n * E_ + e] * W1e[e * H_ + h];
            logit_e += __tanhf(acc) * W2e[h];
        }
        const float score = 1.f / (1.f + __expf(-logit_e));

        float logit_n = b2n[0];
        #pragma unroll
        for (int h = 0; h < H_; h++) {
            float acc = b1n[h];
            #pragma unroll
            for (int d = 0; d < D_; d++)
                acc += node_feats[n * D_ + d] * W1n[d * H_ + h];
            logit_n += __tanhf(acc) * W2n[h];
        }
        const float cond = 1.f / (1.f + __expf(-logit_n));

        const float s = score * cond;
        float m = s;
        #pragma unroll
        for (int off = 16; off; off >>= 1)
            m = fmaxf(m, __shfl_xor_sync(0xffffffffu, m, off));
        const float ex = __expf(s - m);
        float sum = ex;
        #pragma unroll
        for (int off = 16; off; off >>= 1)
            sum += __shfl_xor_sync(0xffffffffu, sum, off);
        w_s[n] = (1.f - SELF_W) * ex / sum;
    }
    __syncthreads();

    float* g_wnm = (float*)g_wnm4;
    float* g_a   = (float*)g_a4;

    const int i = blockIdx.x * PRO_THREADS + tid;  // [0, 4096)
    {
        const float tm = (float)target_mask[i];
        float wn[N_];
        float norm = 1e-8f + SELF_W * tm;
        #pragma unroll
        for (int n = 0; n < N_; n++) {
            wn[n] = w_s[n] * (float)neighbor_masks[n * I_ + i];
            norm += wn[n];
        }
        const float inv = 1.f / norm;
        g_a[i] = SELF_W * tm * inv;
        #pragma unroll
        for (int n = 0; n < N_; n++)
            g_wnm[n * I_ + i] = wn[n] * inv;
    }

    if (i < O_) {
        float acc = SELF_W * target_b[i];
        #pragma unroll
        for (int n = 0; n < N_; n++)
            acc += w_s[n] * neighbor_b[n * O_ + i];
        out_b[i] = acc;
    }
}

// ---------------------------------------------------------------------------
// Main: out_W[o,i] = target_W[o,i]*a[i] + sum_n wnm[n,i]*neighbor_W[n,o,i]
// R2/R4/R7 winner structure: persistent grid-stride, idx recomputed per
// iteration (short live ranges -> 64 regs -> 4 blocks/SM), OB=4 for maximum
// wnm register reuse. PDL: blocks are scheduled while the prologue runs;
// gridDepSync gates the first read of g_a4 / g_wnm4.
// BODY DELIBERATELY UNTOUCHED (replay 168.3-169.8us, 84-85% DRAM).
// ---------------------------------------------------------------------------
#define MAIN_BLOCKS 592     // 148 SMs * 4 resident blocks
#define MAIN_THREADS 256

__global__ void __launch_bounds__(MAIN_THREADS)
main_kernel(const float4* __restrict__ tW,
            const float4* __restrict__ nW,
            float4* __restrict__ outW)
{
    cudaGridDependencySynchronize();

    const int total = (O_ / OB) * I4_;   // 524288 tiles
    for (int idx = blockIdx.x * MAIN_THREADS + threadIdx.x;
         idx < total;
         idx += MAIN_BLOCKS * MAIN_THREADS) {

        const int i4 = idx & (I4_ - 1);
        const int o0 = (idx >> 10) * OB;

        const float4 a = g_a4[i4];
        float4 acc[OB];
        #pragma unroll
        for (int oo = 0; oo < OB; oo++) {
            const float4 t = __ldcs(&tW[(size_t)(o0 + oo) * I4_ + i4]);
            acc[oo].x = t.x * a.x;
            acc[oo].y = t.y * a.y;
            acc[oo].z = t.z * a.z;
            acc[oo].w = t.w * a.w;
        }

        #pragma unroll 4
        for (int n = 0; n < N_; n++) {
            const float4 wv = g_wnm4[n * I4_ + i4];          // L1/L2-resident
            const size_t base = (size_t)n * (O_ * I4_);
            #pragma unroll
            for (int oo = 0; oo < OB; oo++) {
                const float4 Wv = __ldcs(&nW[base + (size_t)(o0 + oo) * I4_ + i4]);
                acc[oo].x += wv.x * Wv.x;
                acc[oo].y += wv.y * Wv.y;
                acc[oo].z += wv.z * Wv.z;
                acc[oo].w += wv.w * Wv.w;
            }
        }

        #pragma unroll
        for (int oo = 0; oo < OB; oo++)
            __stcs(&outW[(size_t)(o0 + oo) * I4_ + i4], acc[oo]);
    }
}

// ---------------------------------------------------------------------------
extern "C" void kernel_launch(void* const* d_in, const int* in_sizes, int n_in,
                              void* d_out, int out_size)
{
    const float* edge_feats     = (const float*)d_in[0];
    const float* node_feats     = (const float*)d_in[1];
    const float* W1e            = (const float*)d_in[2];
    const float* b1e            = (const float*)d_in[3];
    const float* W2e            = (const float*)d_in[4];
    const float* b2e            = (const float*)d_in[5];
    const float* W1n            = (const float*)d_in[6];
    const float* b1n            = (const float*)d_in[7];
    const float* W2n            = (const float*)d_in[8];
    const float* b2n            = (const float*)d_in[9];
    const float* target_W       = (const float*)d_in[10];
    const float* neighbor_W     = (const float*)d_in[11];
    const float* target_b       = (const float*)d_in[12];
    const float* neighbor_b     = (const float*)d_in[13];
    const int*   target_mask    = (const int*)d_in[14];
    const int*   neighbor_masks = (const int*)d_in[15];

    float* out   = (float*)d_out;
    float* out_b = out + (size_t)O_ * I_;

    prologue_kernel<<<PRO_BLOCKS, PRO_THREADS>>>(edge_feats, node_feats,
                                                 W1e, b1e, W2e, b2e,
                                                 W1n, b1n, W2n, b2n,
                                                 target_b, neighbor_b,
                                                 target_mask, neighbor_masks,
                                                 out_b);

    // PDL: main blocks scheduled while the prologue runs; gridDepSync inside
    // gates reads of g_a4/g_wnm4.
    {
        cudaLaunchConfig_t cfg = {};
        cfg.gridDim  = dim3(MAIN_BLOCKS, 1, 1);
        cfg.blockDim = dim3(MAIN_THREADS, 1, 1);
        cfg.dynamicSmemBytes = 0;
        cfg.stream = 0;

        cudaLaunchAttribute attrs[1];
        attrs[0].id = cudaLaunchAttributeProgrammaticStreamSerialization;
        attrs[0].val.programmaticStreamSerializationAllowed = 1;
        cfg.attrs = attrs;
        cfg.numAttrs = 1;

        cudaLaunchKernelEx(&cfg, main_kernel,
                           (const float4*)target_W,
                           (const float4*)neighbor_W,
                           (float4*)out);
    }
}

// round 17
// speedup vs baseline: 1.0029x; 1.0015x over previous
#include <cuda_runtime.h>
#include <math.h>

#define N_ 32
#define O_ 2048
#define I_ 4096
#define I4_ (I_/4)          // 1024
#define E_ 3
#define D_ 8
#define H_ 16
#define SELF_W 0.7f
#define OB 4                // o-rows per thread

// Scratch (no allocs allowed)
__device__ float4 g_wnm4[N_ * I4_];   // w[n]*mask[n][i]/norm[i]
__device__ float4 g_a4[I4_];          // 0.7*tm[i]/norm[i]

// ---------------------------------------------------------------------------
// Fused prologue: warp 0 of every block redundantly computes the 32 attention
// weights; all threads then compute the per-column coefficients. The PDL
// trigger fires IMMEDIATELY after the coefficient stores (the only data the
// main kernel reads) so main's gridDepSync releases before the out_b tail.
// 64 blocks x 64 threads.
// ---------------------------------------------------------------------------
#define PRO_BLOCKS 64
#define PRO_THREADS 64

__global__ void __launch_bounds__(PRO_THREADS)
prologue_kernel(const float* __restrict__ edge_feats,
                const float* __restrict__ node_feats,
                const float* __restrict__ W1e, const float* __restrict__ b1e,
                const float* __restrict__ W2e, const float* __restrict__ b2e,
                const float* __restrict__ W1n, const float* __restrict__ b1n,
                const float* __restrict__ W2n, const float* __restrict__ b2n,
                const float* __restrict__ target_b,
                const float* __restrict__ neighbor_b,
                const int*   __restrict__ target_mask,
                const int*   __restrict__ neighbor_masks,
                float* __restrict__ out_b)
{
    __shared__ float w_s[N_];
    const int tid = threadIdx.x;

    if (tid < N_) {
        const int n = tid;
        float logit_e = b2e[0];
        #pragma unroll
        for (int h = 0; h < H_; h++) {
            float acc = b1e[h];
            #pragma unroll
            for (int e = 0; e < E_; e++)
                acc += edge_feats[n * E_ + e] * W1e[e * H_ + h];
            logit_e += __tanhf(acc) * W2e[h];
        }
        const float score = 1.f / (1.f + __expf(-logit_e));

        float logit_n = b2n[0];
        #pragma unroll
        for (int h = 0; h < H_; h++) {
            float acc = b1n[h];
            #pragma unroll
            for (int d = 0; d < D_; d++)
                acc += node_feats[n * D_ + d] * W1n[d * H_ + h];
            logit_n += __tanhf(acc) * W2n[h];
        }
        const float cond = 1.f / (1.f + __expf(-logit_n));

        const float s = score * cond;
        float m = s;
        #pragma unroll
        for (int off = 16; off; off >>= 1)
            m = fmaxf(m, __shfl_xor_sync(0xffffffffu, m, off));
        const float ex = __expf(s - m);
        float sum = ex;
        #pragma unroll
        for (int off = 16; off; off >>= 1)
            sum += __shfl_xor_sync(0xffffffffu, sum, off);
        w_s[n] = (1.f - SELF_W) * ex / sum;
    }
    __syncthreads();

    float* g_wnm = (float*)g_wnm4;
    float* g_a   = (float*)g_a4;

    const int i = blockIdx.x * PRO_THREADS + tid;  // [0, 4096)
    float w_loc[N_];                                // keep weights for out_b tail
    #pragma unroll
    for (int n = 0; n < N_; n++) w_loc[n] = w_s[n];
    {
        const float tm = (float)target_mask[i];
        float wn[N_];
        float norm = 1e-8f + SELF_W * tm;
        #pragma unroll
        for (int n = 0; n < N_; n++) {
            wn[n] = w_loc[n] * (float)neighbor_masks[n * I_ + i];
            norm += wn[n];
        }
        const float inv = 1.f / norm;
        g_a[i] = SELF_W * tm * inv;
        #pragma unroll
        for (int n = 0; n < N_; n++)
            g_wnm[n * I_ + i] = wn[n] * inv;
    }

    // Coefficients done — release the dependent main kernel NOW.
    cudaTriggerProgrammaticLaunchCompletion();

    // out_b tail runs concurrently with main's ramp-up (main never reads it;
    // harness ordering is guaranteed by stream/graph completion).
    if (i < O_) {
        float acc = SELF_W * target_b[i];
        #pragma unroll
        for (int n = 0; n < N_; n++)
            acc += w_loc[n] * neighbor_b[n * O_ + i];
        out_b[i] = acc;
    }
}

// ---------------------------------------------------------------------------
// Main: out_W[o,i] = target_W[o,i]*a[i] + sum_n wnm[n,i]*neighbor_W[n,o,i]
// R2/R4/R7 winner structure: persistent grid-stride, idx recomputed per
// iteration (short live ranges -> 64 regs -> 4 blocks/SM), OB=4 for maximum
// wnm register reuse. PDL: blocks are scheduled while the prologue runs;
// gridDepSync gates the first read of g_a4 / g_wnm4.
// BODY DELIBERATELY UNTOUCHED (replay 168.3-169.8us, 84-85% DRAM).
// ---------------------------------------------------------------------------
#define MAIN_BLOCKS 592     // 148 SMs * 4 resident blocks
#define MAIN_THREADS 256

__global__ void __launch_bounds__(MAIN_THREADS)
main_kernel(const float4* __restrict__ tW,
            const float4* __restrict__ nW,
            float4* __restrict__ outW)
{
    cudaGridDependencySynchronize();

    const int total = (O_ / OB) * I4_;   // 524288 tiles
    for (int idx = blockIdx.x * MAIN_THREADS + threadIdx.x;
         idx < total;
         idx += MAIN_BLOCKS * MAIN_THREADS) {

        const int i4 = idx & (I4_ - 1);
        const int o0 = (idx >> 10) * OB;

        const float4 a = g_a4[i4];
        float4 acc[OB];
        #pragma unroll
        for (int oo = 0; oo < OB; oo++) {
            const float4 t = __ldcs(&tW[(size_t)(o0 + oo) * I4_ + i4]);
            acc[oo].x = t.x * a.x;
            acc[oo].y = t.y * a.y;
            acc[oo].z = t.z * a.z;
            acc[oo].w = t.w * a.w;
        }

        #pragma unroll 4
        for (int n = 0; n < N_; n++) {
            const float4 wv = g_wnm4[n * I4_ + i4];          // L1/L2-resident
            const size_t base = (size_t)n * (O_ * I4_);
            #pragma unroll
            for (int oo = 0; oo < OB; oo++) {
                const float4 Wv = __ldcs(&nW[base + (size_t)(o0 + oo) * I4_ + i4]);
                acc[oo].x += wv.x * Wv.x;
                acc[oo].y += wv.y * Wv.y;
                acc[oo].z += wv.z * Wv.z;
                acc[oo].w += wv.w * Wv.w;
            }
        }

        #pragma unroll
        for (int oo = 0; oo < OB; oo++)
            __stcs(&outW[(size_t)(o0 + oo) * I4_ + i4], acc[oo]);
    }
}

// ---------------------------------------------------------------------------
extern "C" void kernel_launch(void* const* d_in, const int* in_sizes, int n_in,
                              void* d_out, int out_size)
{
    const float* edge_feats     = (const float*)d_in[0];
    const float* node_feats     = (const float*)d_in[1];
    const float* W1e            = (const float*)d_in[2];
    const float* b1e            = (const float*)d_in[3];
    const float* W2e            = (const float*)d_in[4];
    const float* b2e            = (const float*)d_in[5];
    const float* W1n            = (const float*)d_in[6];
    const float* b1n            = (const float*)d_in[7];
    const float* W2n            = (const float*)d_in[8];
    const float* b2n            = (const float*)d_in[9];
    const float* target_W       = (const float*)d_in[10];
    const float* neighbor_W     = (const float*)d_in[11];
    const float* target_b       = (const float*)d_in[12];
    const float* neighbor_b     = (const float*)d_in[13];
    const int*   target_mask    = (const int*)d_in[14];
    const int*   neighbor_masks = (const int*)d_in[15];

    float* out   = (float*)d_out;
    float* out_b = out + (size_t)O_ * I_;

    prologue_kernel<<<PRO_BLOCKS, PRO_THREADS>>>(edge_feats, node_feats,
                                                 W1e, b1e, W2e, b2e,
                                                 W1n, b1n, W2n, b2n,
                                                 target_b, neighbor_b,
                                                 target_mask, neighbor_masks,
                                                 out_b);

    // PDL: main blocks scheduled while the prologue runs; gridDepSync inside
    // gates reads of g_a4/g_wnm4 (released by the early trigger).
    {
        cudaLaunchConfig_t cfg = {};
        cfg.gridDim  = dim3(MAIN_BLOCKS, 1, 1);
        cfg.blockDim = dim3(MAIN_THREADS, 1, 1);
        cfg.dynamicSmemBytes = 0;
        cfg.stream = 0;

        cudaLaunchAttribute attrs[1];
        attrs[0].id = cudaLaunchAttributeProgrammaticStreamSerialization;
        attrs[0].val.programmaticStreamSerializationAllowed = 1;
        cfg.attrs = attrs;
        cfg.numAttrs = 1;

        cudaLaunchKernelEx(&cfg, main_kernel,
                           (const float4*)target_W,
                           (const float4*)neighbor_W,
                           (float4*)out);
    }
}